// round 2
// baseline (speedup 1.0000x reference)
#include <cuda_runtime.h>
#include <cuda_bf16.h>
#include <math.h>

// Problem constants (fixed shapes for this problem)
#define NNODE   50000
#define NEDGE   800000
#define ETOT    (NEDGE + NNODE)
#define IN_DIM  256
#define FEAT    128        // HEADS*NHID == OUT_DIM == 128
#define HEADS   4
#define NHID    32
#define NEG_SLOPE 0.2f

// ---------------- device scratch (static, no allocation) ----------------
__device__ float g_bufA[NNODE * FEAT];   // h1 then h2
__device__ float g_bufB[NNODE * FEAT];   // layer-1 aggregation target -> elu feat
__device__ float g_as[NNODE * HEADS];    // alpha_src (layer1: N*4, layer2: first N)
__device__ float g_ad[NNODE * HEADS];
__device__ float g_s[NNODE * HEADS];     // softmax denominators
__device__ float g_expE[ETOT * HEADS];   // per-edge exp(e) (layer1: E*4, layer2: first E)

// ---------------- utility ----------------
__global__ void zero_kernel(float* __restrict__ p, int n) {
    int i = blockIdx.x * blockDim.x + threadIdx.x;
    int stride = gridDim.x * blockDim.x;
    for (; i < n; i += stride) p[i] = 0.0f;
}

// ---------------- fp32 tiled GEMM: C[M,128] = A[M,K] * B[K,128] ----------------
template <int K>
__global__ void __launch_bounds__(256) gemm128_kernel(
    const float* __restrict__ A, const float* __restrict__ B,
    float* __restrict__ C, int M)
{
    __shared__ float As[64][16];
    __shared__ float Bs[16][128];

    const int t  = threadIdx.x;
    const int tx = t & 15;        // 0..15 -> col group of 8
    const int ty = t >> 4;        // 0..15 -> row group of 4
    const int rowBase = blockIdx.x * 64;

    float acc[4][8];
#pragma unroll
    for (int i = 0; i < 4; i++)
#pragma unroll
        for (int j = 0; j < 8; j++) acc[i][j] = 0.0f;

    const int ar = t >> 2;             // 0..63
    const int ac = (t & 3) * 4;        // 0,4,8,12
    const int br = t >> 5;             // 0..7
    const int bc = (t & 31) * 4;       // 0..124

    for (int k0 = 0; k0 < K; k0 += 16) {
        // load A tile (64 x 16)
        int grow = rowBase + ar;
        float4 av;
        if (grow < M) av = *(const float4*)&A[(long)grow * K + k0 + ac];
        else          av = make_float4(0.f, 0.f, 0.f, 0.f);
        *(float4*)&As[ar][ac] = av;
        // load B tile (16 x 128)
        *(float4*)&Bs[br][bc]     = *(const float4*)&B[(long)(k0 + br) * 128 + bc];
        *(float4*)&Bs[br + 8][bc] = *(const float4*)&B[(long)(k0 + br + 8) * 128 + bc];
        __syncthreads();

#pragma unroll
        for (int k = 0; k < 16; k++) {
            float a[4], b[8];
#pragma unroll
            for (int i = 0; i < 4; i++) a[i] = As[ty * 4 + i][k];
#pragma unroll
            for (int j = 0; j < 8; j++) b[j] = Bs[k][tx * 8 + j];
#pragma unroll
            for (int i = 0; i < 4; i++)
#pragma unroll
                for (int j = 0; j < 8; j++) acc[i][j] = fmaf(a[i], b[j], acc[i][j]);
        }
        __syncthreads();
    }

#pragma unroll
    for (int i = 0; i < 4; i++) {
        int r = rowBase + ty * 4 + i;
        if (r < M) {
            float4 v0 = make_float4(acc[i][0], acc[i][1], acc[i][2], acc[i][3]);
            float4 v1 = make_float4(acc[i][4], acc[i][5], acc[i][6], acc[i][7]);
            *(float4*)&C[(long)r * 128 + tx * 8]     = v0;
            *(float4*)&C[(long)r * 128 + tx * 8 + 4] = v1;
        }
    }
}

// ---------------- layer-1 per-node attention coefficients ----------------
// thread = (node, head); sum over 32 channels
__global__ void alpha1_kernel(const float* __restrict__ h,
                              const float* __restrict__ a_src,
                              const float* __restrict__ a_dst,
                              float* __restrict__ as_, float* __restrict__ ad_,
                              int n)
{
    int idx = blockIdx.x * blockDim.x + threadIdx.x;
    if (idx >= n * HEADS) return;
    int node = idx >> 2, head = idx & 3;
    const float* hp = h + (long)node * FEAT + head * NHID;
    const float* sp = a_src + head * NHID;
    const float* dp = a_dst + head * NHID;
    float ss = 0.f, sd = 0.f;
#pragma unroll
    for (int c = 0; c < NHID; c++) {
        float v = hp[c];
        ss = fmaf(v, __ldg(&sp[c]), ss);
        sd = fmaf(v, __ldg(&dp[c]), sd);
    }
    as_[idx] = ss;
    ad_[idx] = sd;
}

// ---------------- layer-2 per-node attention coefficients (warp per node) -----
__global__ void alpha2_kernel(const float* __restrict__ h,
                              const float* __restrict__ a_src,
                              const float* __restrict__ a_dst,
                              float* __restrict__ as_, float* __restrict__ ad_,
                              int n)
{
    int g = blockIdx.x * blockDim.x + threadIdx.x;
    int node = g >> 5, lane = g & 31;
    if (node >= n) return;
    float4 v  = *(const float4*)&h[(long)node * FEAT + lane * 4];
    float4 s4 = *(const float4*)&a_src[lane * 4];
    float4 d4 = *(const float4*)&a_dst[lane * 4];
    float ss = v.x * s4.x + v.y * s4.y + v.z * s4.z + v.w * s4.w;
    float sd = v.x * d4.x + v.y * d4.y + v.z * d4.z + v.w * d4.w;
#pragma unroll
    for (int o = 16; o > 0; o >>= 1) {
        ss += __shfl_down_sync(0xFFFFFFFFu, ss, o);
        sd += __shfl_down_sync(0xFFFFFFFFu, sd, o);
    }
    if (lane == 0) { as_[node] = ss; ad_[node] = sd; }
}

__device__ __forceinline__ float lrelu(float x) { return x > 0.f ? x : NEG_SLOPE * x; }

// ---------------- layer-1 edge pass A: exp(e) + segment-sum -------------------
__global__ void edge_att4_kernel(const int* __restrict__ ei, int E, int Etot,
                                 const float* __restrict__ as_,
                                 const float* __restrict__ ad_,
                                 float* __restrict__ expE, float* __restrict__ s)
{
    int e = blockIdx.x * blockDim.x + threadIdx.x;
    if (e >= Etot) return;
    int src, dst;
    if (e < E) { src = ei[e]; dst = ei[E + e]; }
    else       { src = dst = e - E; }
    float4 a = *(const float4*)&as_[src * 4];
    float4 b = *(const float4*)&ad_[dst * 4];
    float4 w;
    w.x = expf(lrelu(a.x + b.x));
    w.y = expf(lrelu(a.y + b.y));
    w.z = expf(lrelu(a.z + b.z));
    w.w = expf(lrelu(a.w + b.w));
    *(float4*)&expE[e * 4] = w;
    atomicAdd(&s[dst * 4 + 0], w.x);
    atomicAdd(&s[dst * 4 + 1], w.y);
    atomicAdd(&s[dst * 4 + 2], w.z);
    atomicAdd(&s[dst * 4 + 3], w.w);
}

// ---------------- layer-1 edge pass B: weighted scatter aggregation -----------
// warp per edge; lane handles channels [lane*4, lane*4+4) -> head = lane/8
__global__ void edge_agg4_kernel(const int* __restrict__ ei, int E, int Etot,
                                 const float* __restrict__ h,
                                 const float* __restrict__ expE,
                                 const float* __restrict__ s,
                                 float* __restrict__ out)
{
    int g = blockIdx.x * blockDim.x + threadIdx.x;
    int e = g >> 5, lane = g & 31;
    if (e >= Etot) return;
    int src, dst;
    if (e < E) { src = __ldg(&ei[e]); dst = __ldg(&ei[E + e]); }
    else       { src = dst = e - E; }
    int head = lane >> 3;
    float w = __ldg(&expE[e * 4 + head]) / (__ldg(&s[dst * 4 + head]) + 1e-16f);
    float4 v = *(const float4*)&h[(long)src * FEAT + lane * 4];
    float* o = out + (long)dst * FEAT + lane * 4;
    atomicAdd(o + 0, v.x * w);
    atomicAdd(o + 1, v.y * w);
    atomicAdd(o + 2, v.z * w);
    atomicAdd(o + 3, v.w * w);
}

// ---------------- layer-2 edge pass A (1 head) --------------------------------
__global__ void edge_att1_kernel(const int* __restrict__ ei, int E, int Etot,
                                 const float* __restrict__ as_,
                                 const float* __restrict__ ad_,
                                 float* __restrict__ expE, float* __restrict__ s)
{
    int e = blockIdx.x * blockDim.x + threadIdx.x;
    if (e >= Etot) return;
    int src, dst;
    if (e < E) { src = ei[e]; dst = ei[E + e]; }
    else       { src = dst = e - E; }
    float w = expf(lrelu(__ldg(&as_[src]) + __ldg(&ad_[dst])));
    expE[e] = w;
    atomicAdd(&s[dst], w);
}

// ---------------- layer-2 edge pass B (1 head) --------------------------------
__global__ void edge_agg1_kernel(const int* __restrict__ ei, int E, int Etot,
                                 const float* __restrict__ h,
                                 const float* __restrict__ expE,
                                 const float* __restrict__ s,
                                 float* __restrict__ out)
{
    int g = blockIdx.x * blockDim.x + threadIdx.x;
    int e = g >> 5, lane = g & 31;
    if (e >= Etot) return;
    int src, dst;
    if (e < E) { src = __ldg(&ei[e]); dst = __ldg(&ei[E + e]); }
    else       { src = dst = e - E; }
    float w = __ldg(&expE[e]) / (__ldg(&s[dst]) + 1e-16f);
    float4 v = *(const float4*)&h[(long)src * FEAT + lane * 4];
    float* o = out + (long)dst * FEAT + lane * 4;
    atomicAdd(o + 0, v.x * w);
    atomicAdd(o + 1, v.y * w);
    atomicAdd(o + 2, v.z * w);
    atomicAdd(o + 3, v.w * w);
}

// ---------------- bias + ELU (layer-1 epilogue) -------------------------------
__global__ void elu_bias_kernel(float* __restrict__ buf, const float* __restrict__ b, int n)
{
    int i = blockIdx.x * blockDim.x + threadIdx.x;
    if (i >= n) return;
    float v = buf[i] + __ldg(&b[i & (FEAT - 1)]);
    buf[i] = v > 0.f ? v : expm1f(v);
}

// ---------------- final bias add ---------------------------------------------
__global__ void bias_kernel(float* __restrict__ buf, const float* __restrict__ b, int n)
{
    int i = blockIdx.x * blockDim.x + threadIdx.x;
    if (i >= n) return;
    buf[i] += __ldg(&b[i & (FEAT - 1)]);
}

// =============================================================================
extern "C" void kernel_launch(void* const* d_in, const int* in_sizes, int n_in,
                              void* d_out, int out_size)
{
    const float* x        = (const float*)d_in[0];
    const int*   ei       = (const int*)  d_in[1];
    const float* W1       = (const float*)d_in[2];
    const float* att_src1 = (const float*)d_in[3];
    const float* att_dst1 = (const float*)d_in[4];
    const float* b1       = (const float*)d_in[5];
    const float* W2       = (const float*)d_in[6];
    const float* att_src2 = (const float*)d_in[7];
    const float* att_dst2 = (const float*)d_in[8];
    const float* b2       = (const float*)d_in[9];
    float* out = (float*)d_out;

    const int N    = in_sizes[0] / IN_DIM;   // 50000
    const int E    = in_sizes[1] / 2;        // 800000
    const int Etot = E + N;                  // 850000

    float *bufA, *bufB, *as_, *ad_, *s_, *expE;
    cudaGetSymbolAddress((void**)&bufA, g_bufA);
    cudaGetSymbolAddress((void**)&bufB, g_bufB);
    cudaGetSymbolAddress((void**)&as_,  g_as);
    cudaGetSymbolAddress((void**)&ad_,  g_ad);
    cudaGetSymbolAddress((void**)&s_,   g_s);
    cudaGetSymbolAddress((void**)&expE, g_expE);

    const int ZB = 256;
    // ---- Layer 1 ----
    zero_kernel<<<(N * HEADS + ZB - 1) / ZB, ZB>>>(s_, N * HEADS);
    zero_kernel<<<2048, ZB>>>(bufB, N * FEAT);

    gemm128_kernel<IN_DIM><<<(N + 63) / 64, 256>>>(x, W1, bufA, N);
    alpha1_kernel<<<(N * HEADS + 127) / 128, 128>>>(bufA, att_src1, att_dst1, as_, ad_, N);
    edge_att4_kernel<<<(Etot + 255) / 256, 256>>>(ei, E, Etot, as_, ad_, expE, s_);
    {
        long threads = (long)Etot * 32;
        edge_agg4_kernel<<<(int)((threads + 255) / 256), 256>>>(ei, E, Etot, bufA, expE, s_, bufB);
    }
    elu_bias_kernel<<<(N * FEAT + 255) / 256, 256>>>(bufB, b1, N * FEAT);

    // ---- Layer 2 ----
    zero_kernel<<<(N + ZB - 1) / ZB, ZB>>>(s_, N);
    zero_kernel<<<2048, ZB>>>(out, N * FEAT);

    gemm128_kernel<FEAT><<<(N + 63) / 64, 256>>>(bufB, W2, bufA, N);
    alpha2_kernel<<<(N * 32 + 255) / 256, 256>>>(bufA, att_src2, att_dst2, as_, ad_, N);
    edge_att1_kernel<<<(Etot + 255) / 256, 256>>>(ei, E, Etot, as_, ad_, expE, s_);
    {
        long threads = (long)Etot * 32;
        edge_agg1_kernel<<<(int)((threads + 255) / 256), 256>>>(ei, E, Etot, bufA, expE, s_, out);
    }
    bias_kernel<<<(N * FEAT + 255) / 256, 256>>>(out, b2, N * FEAT);
}

// round 3
// speedup vs baseline: 1.0058x; 1.0058x over previous
#include <cuda_runtime.h>
#include <cuda_bf16.h>
#include <math.h>

// Problem constants (fixed shapes for this problem)
#define NNODE   50000
#define NEDGE   800000
#define ETOT    (NEDGE + NNODE)
#define IN_DIM  256
#define FEAT    128        // HEADS*NHID == OUT_DIM == 128
#define HEADS   4
#define NHID    32
#define NEG_SLOPE 0.2f

// ---------------- device scratch (static, no allocation) ----------------
__device__ float g_bufA[NNODE * FEAT];   // h1 then h2
__device__ float g_bufB[NNODE * FEAT];   // layer-1 aggregation target -> elu feat
__device__ float g_as[NNODE * HEADS];    // alpha_src (layer1: N*4, layer2: first N)
__device__ float g_ad[NNODE * HEADS];
__device__ float g_s[NNODE * HEADS];     // softmax denominators
__device__ float g_expE[ETOT * HEADS];   // per-edge exp(e) (layer1: E*4, layer2: first E)

// ---------------- utility ----------------
__global__ void zero_kernel(float* __restrict__ p, int n) {
    int i = blockIdx.x * blockDim.x + threadIdx.x;
    int stride = gridDim.x * blockDim.x;
    for (; i < n; i += stride) p[i] = 0.0f;
}

// ---------------- fp32 tiled GEMM: C[M,128] = A[M,K] * B[K,128] ----------------
template <int K>
__global__ void __launch_bounds__(256) gemm128_kernel(
    const float* __restrict__ A, const float* __restrict__ B,
    float* __restrict__ C, int M)
{
    __shared__ float As[64][16];
    __shared__ float Bs[16][128];

    const int t  = threadIdx.x;
    const int tx = t & 15;        // 0..15 -> col group of 8
    const int ty = t >> 4;        // 0..15 -> row group of 4
    const int rowBase = blockIdx.x * 64;

    float acc[4][8];
#pragma unroll
    for (int i = 0; i < 4; i++)
#pragma unroll
        for (int j = 0; j < 8; j++) acc[i][j] = 0.0f;

    const int ar = t >> 2;             // 0..63
    const int ac = (t & 3) * 4;        // 0,4,8,12
    const int br = t >> 5;             // 0..7
    const int bc = (t & 31) * 4;       // 0..124

    for (int k0 = 0; k0 < K; k0 += 16) {
        // load A tile (64 x 16)
        int grow = rowBase + ar;
        float4 av;
        if (grow < M) av = *(const float4*)&A[(long)grow * K + k0 + ac];
        else          av = make_float4(0.f, 0.f, 0.f, 0.f);
        *(float4*)&As[ar][ac] = av;
        // load B tile (16 x 128)
        *(float4*)&Bs[br][bc]     = *(const float4*)&B[(long)(k0 + br) * 128 + bc];
        *(float4*)&Bs[br + 8][bc] = *(const float4*)&B[(long)(k0 + br + 8) * 128 + bc];
        __syncthreads();

#pragma unroll
        for (int k = 0; k < 16; k++) {
            float a[4], b[8];
#pragma unroll
            for (int i = 0; i < 4; i++) a[i] = As[ty * 4 + i][k];
#pragma unroll
            for (int j = 0; j < 8; j++) b[j] = Bs[k][tx * 8 + j];
#pragma unroll
            for (int i = 0; i < 4; i++)
#pragma unroll
                for (int j = 0; j < 8; j++) acc[i][j] = fmaf(a[i], b[j], acc[i][j]);
        }
        __syncthreads();
    }

#pragma unroll
    for (int i = 0; i < 4; i++) {
        int r = rowBase + ty * 4 + i;
        if (r < M) {
            float4 v0 = make_float4(acc[i][0], acc[i][1], acc[i][2], acc[i][3]);
            float4 v1 = make_float4(acc[i][4], acc[i][5], acc[i][6], acc[i][7]);
            *(float4*)&C[(long)r * 128 + tx * 8]     = v0;
            *(float4*)&C[(long)r * 128 + tx * 8 + 4] = v1;
        }
    }
}

// ---------------- layer-1 per-node attention coefficients ----------------
// thread = (node, head); sum over 32 channels
__global__ void alpha1_kernel(const float* __restrict__ h,
                              const float* __restrict__ a_src,
                              const float* __restrict__ a_dst,
                              float* __restrict__ as_, float* __restrict__ ad_,
                              int n)
{
    int idx = blockIdx.x * blockDim.x + threadIdx.x;
    if (idx >= n * HEADS) return;
    int node = idx >> 2, head = idx & 3;
    const float* hp = h + (long)node * FEAT + head * NHID;
    const float* sp = a_src + head * NHID;
    const float* dp = a_dst + head * NHID;
    float ss = 0.f, sd = 0.f;
#pragma unroll
    for (int c = 0; c < NHID; c++) {
        float v = hp[c];
        ss = fmaf(v, __ldg(&sp[c]), ss);
        sd = fmaf(v, __ldg(&dp[c]), sd);
    }
    as_[idx] = ss;
    ad_[idx] = sd;
}

// ---------------- layer-2 per-node attention coefficients (warp per node) -----
__global__ void alpha2_kernel(const float* __restrict__ h,
                              const float* __restrict__ a_src,
                              const float* __restrict__ a_dst,
                              float* __restrict__ as_, float* __restrict__ ad_,
                              int n)
{
    int g = blockIdx.x * blockDim.x + threadIdx.x;
    int node = g >> 5, lane = g & 31;
    if (node >= n) return;
    float4 v  = *(const float4*)&h[(long)node * FEAT + lane * 4];
    float4 s4 = *(const float4*)&a_src[lane * 4];
    float4 d4 = *(const float4*)&a_dst[lane * 4];
    float ss = v.x * s4.x + v.y * s4.y + v.z * s4.z + v.w * s4.w;
    float sd = v.x * d4.x + v.y * d4.y + v.z * d4.z + v.w * d4.w;
#pragma unroll
    for (int o = 16; o > 0; o >>= 1) {
        ss += __shfl_down_sync(0xFFFFFFFFu, ss, o);
        sd += __shfl_down_sync(0xFFFFFFFFu, sd, o);
    }
    if (lane == 0) { as_[node] = ss; ad_[node] = sd; }
}

__device__ __forceinline__ float lrelu(float x) { return x > 0.f ? x : NEG_SLOPE * x; }

// ---------------- layer-1 edge pass A: exp(e) + segment-sum -------------------
__global__ void edge_att4_kernel(const int* __restrict__ ei, int E, int Etot,
                                 const float* __restrict__ as_,
                                 const float* __restrict__ ad_,
                                 float* __restrict__ expE, float* __restrict__ s)
{
    int e = blockIdx.x * blockDim.x + threadIdx.x;
    if (e >= Etot) return;
    int src, dst;
    if (e < E) { src = ei[e]; dst = ei[E + e]; }
    else       { src = dst = e - E; }
    float4 a = *(const float4*)&as_[src * 4];
    float4 b = *(const float4*)&ad_[dst * 4];
    float4 w;
    w.x = expf(lrelu(a.x + b.x));
    w.y = expf(lrelu(a.y + b.y));
    w.z = expf(lrelu(a.z + b.z));
    w.w = expf(lrelu(a.w + b.w));
    *(float4*)&expE[e * 4] = w;
    atomicAdd(&s[dst * 4 + 0], w.x);
    atomicAdd(&s[dst * 4 + 1], w.y);
    atomicAdd(&s[dst * 4 + 2], w.z);
    atomicAdd(&s[dst * 4 + 3], w.w);
}

// ---------------- layer-1 edge pass B: weighted scatter aggregation -----------
// warp per edge; lane handles channels [lane*4, lane*4+4) -> head = lane/8
__global__ void edge_agg4_kernel(const int* __restrict__ ei, int E, int Etot,
                                 const float* __restrict__ h,
                                 const float* __restrict__ expE,
                                 const float* __restrict__ s,
                                 float* __restrict__ out)
{
    int g = blockIdx.x * blockDim.x + threadIdx.x;
    int e = g >> 5, lane = g & 31;
    if (e >= Etot) return;
    int src, dst;
    if (e < E) { src = __ldg(&ei[e]); dst = __ldg(&ei[E + e]); }
    else       { src = dst = e - E; }
    int head = lane >> 3;
    float w = __ldg(&expE[e * 4 + head]) / (__ldg(&s[dst * 4 + head]) + 1e-16f);
    float4 v = *(const float4*)&h[(long)src * FEAT + lane * 4];
    float* o = out + (long)dst * FEAT + lane * 4;
    atomicAdd(o + 0, v.x * w);
    atomicAdd(o + 1, v.y * w);
    atomicAdd(o + 2, v.z * w);
    atomicAdd(o + 3, v.w * w);
}

// ---------------- layer-2 edge pass A (1 head) --------------------------------
__global__ void edge_att1_kernel(const int* __restrict__ ei, int E, int Etot,
                                 const float* __restrict__ as_,
                                 const float* __restrict__ ad_,
                                 float* __restrict__ expE, float* __restrict__ s)
{
    int e = blockIdx.x * blockDim.x + threadIdx.x;
    if (e >= Etot) return;
    int src, dst;
    if (e < E) { src = ei[e]; dst = ei[E + e]; }
    else       { src = dst = e - E; }
    float w = expf(lrelu(__ldg(&as_[src]) + __ldg(&ad_[dst])));
    expE[e] = w;
    atomicAdd(&s[dst], w);
}

// ---------------- layer-2 edge pass B (1 head) --------------------------------
__global__ void edge_agg1_kernel(const int* __restrict__ ei, int E, int Etot,
                                 const float* __restrict__ h,
                                 const float* __restrict__ expE,
                                 const float* __restrict__ s,
                                 float* __restrict__ out)
{
    int g = blockIdx.x * blockDim.x + threadIdx.x;
    int e = g >> 5, lane = g & 31;
    if (e >= Etot) return;
    int src, dst;
    if (e < E) { src = __ldg(&ei[e]); dst = __ldg(&ei[E + e]); }
    else       { src = dst = e - E; }
    float w = __ldg(&expE[e]) / (__ldg(&s[dst]) + 1e-16f);
    float4 v = *(const float4*)&h[(long)src * FEAT + lane * 4];
    float* o = out + (long)dst * FEAT + lane * 4;
    atomicAdd(o + 0, v.x * w);
    atomicAdd(o + 1, v.y * w);
    atomicAdd(o + 2, v.z * w);
    atomicAdd(o + 3, v.w * w);
}

// ---------------- bias + ELU (layer-1 epilogue) -------------------------------
__global__ void elu_bias_kernel(float* __restrict__ buf, const float* __restrict__ b, int n)
{
    int i = blockIdx.x * blockDim.x + threadIdx.x;
    if (i >= n) return;
    float v = buf[i] + __ldg(&b[i & (FEAT - 1)]);
    buf[i] = v > 0.f ? v : expm1f(v);
}

// ---------------- final bias add ---------------------------------------------
__global__ void bias_kernel(float* __restrict__ buf, const float* __restrict__ b, int n)
{
    int i = blockIdx.x * blockDim.x + threadIdx.x;
    if (i >= n) return;
    buf[i] += __ldg(&b[i & (FEAT - 1)]);
}

// =============================================================================
extern "C" void kernel_launch(void* const* d_in, const int* in_sizes, int n_in,
                              void* d_out, int out_size)
{
    const float* x        = (const float*)d_in[0];
    const int*   ei       = (const int*)  d_in[1];
    const float* W1       = (const float*)d_in[2];
    const float* att_src1 = (const float*)d_in[3];
    const float* att_dst1 = (const float*)d_in[4];
    const float* b1       = (const float*)d_in[5];
    const float* W2       = (const float*)d_in[6];
    const float* att_src2 = (const float*)d_in[7];
    const float* att_dst2 = (const float*)d_in[8];
    const float* b2       = (const float*)d_in[9];
    float* out = (float*)d_out;

    const int N    = in_sizes[0] / IN_DIM;   // 50000
    const int E    = in_sizes[1] / 2;        // 800000
    const int Etot = E + N;                  // 850000

    float *bufA, *bufB, *as_, *ad_, *s_, *expE;
    cudaGetSymbolAddress((void**)&bufA, g_bufA);
    cudaGetSymbolAddress((void**)&bufB, g_bufB);
    cudaGetSymbolAddress((void**)&as_,  g_as);
    cudaGetSymbolAddress((void**)&ad_,  g_ad);
    cudaGetSymbolAddress((void**)&s_,   g_s);
    cudaGetSymbolAddress((void**)&expE, g_expE);

    const int ZB = 256;
    // ---- Layer 1 ----
    zero_kernel<<<(N * HEADS + ZB - 1) / ZB, ZB>>>(s_, N * HEADS);
    zero_kernel<<<2048, ZB>>>(bufB, N * FEAT);

    gemm128_kernel<IN_DIM><<<(N + 63) / 64, 256>>>(x, W1, bufA, N);
    alpha1_kernel<<<(N * HEADS + 127) / 128, 128>>>(bufA, att_src1, att_dst1, as_, ad_, N);
    edge_att4_kernel<<<(Etot + 255) / 256, 256>>>(ei, E, Etot, as_, ad_, expE, s_);
    {
        long threads = (long)Etot * 32;
        edge_agg4_kernel<<<(int)((threads + 255) / 256), 256>>>(ei, E, Etot, bufA, expE, s_, bufB);
    }
    elu_bias_kernel<<<(N * FEAT + 255) / 256, 256>>>(bufB, b1, N * FEAT);

    // ---- Layer 2 ----
    zero_kernel<<<(N + ZB - 1) / ZB, ZB>>>(s_, N);
    zero_kernel<<<2048, ZB>>>(out, N * FEAT);

    gemm128_kernel<FEAT><<<(N + 63) / 64, 256>>>(bufB, W2, bufA, N);
    alpha2_kernel<<<(N * 32 + 255) / 256, 256>>>(bufA, att_src2, att_dst2, as_, ad_, N);
    edge_att1_kernel<<<(Etot + 255) / 256, 256>>>(ei, E, Etot, as_, ad_, expE, s_);
    {
        long threads = (long)Etot * 32;
        edge_agg1_kernel<<<(int)((threads + 255) / 256), 256>>>(ei, E, Etot, bufA, expE, s_, out);
    }
    bias_kernel<<<(N * FEAT + 255) / 256, 256>>>(out, b2, N * FEAT);
}

// round 4
// speedup vs baseline: 1.6396x; 1.6301x over previous
#include <cuda_runtime.h>
#include <cuda_bf16.h>
#include <math.h>

#define NNODE   50000
#define NEDGE   800000
#define ETOT    (NEDGE + NNODE)
#define IN_DIM  256
#define FEAT    128
#define HEADS   4
#define NHID    32
#define NEG_SLOPE 0.2f

// ---------------- device scratch (static, no allocation) ----------------
__device__ float g_bufA[NNODE * FEAT];   // h1 then h2
__device__ float g_bufB[NNODE * FEAT];   // layer-1 aggregation target -> elu feat
__device__ float g_as[NNODE * HEADS];
__device__ float g_ad[NNODE * HEADS];
__device__ float g_s[NNODE * HEADS];     // softmax denominators

__device__ __forceinline__ float lrelu(float x) { return x > 0.f ? x : NEG_SLOPE * x; }

__device__ __forceinline__ void red_add_f32(float* addr, float v) {
    asm volatile("red.global.add.f32 [%0], %1;" :: "l"(addr), "f"(v) : "memory");
}
__device__ __forceinline__ void red_add_v4(float* addr, float a, float b, float c, float d) {
    asm volatile("red.global.add.v4.f32 [%0], {%1,%2,%3,%4};"
                 :: "l"(addr), "f"(a), "f"(b), "f"(c), "f"(d) : "memory");
}

// ---------------- utility ----------------
__global__ void zero_kernel(float* __restrict__ p, int n) {
    int i = blockIdx.x * blockDim.x + threadIdx.x;
    int stride = gridDim.x * blockDim.x;
    for (; i < n; i += stride) p[i] = 0.0f;
}

// ---------------- fp32 tiled GEMM: C[M,128] = A[M,K] * B[K,128] ----------------
template <int K>
__global__ void __launch_bounds__(256) gemm128_kernel(
    const float* __restrict__ A, const float* __restrict__ B,
    float* __restrict__ C, int M)
{
    __shared__ float As[64][16];
    __shared__ float Bs[16][128];

    const int t  = threadIdx.x;
    const int tx = t & 15;
    const int ty = t >> 4;
    const int rowBase = blockIdx.x * 64;

    float acc[4][8];
#pragma unroll
    for (int i = 0; i < 4; i++)
#pragma unroll
        for (int j = 0; j < 8; j++) acc[i][j] = 0.0f;

    const int ar = t >> 2;
    const int ac = (t & 3) * 4;
    const int br = t >> 5;
    const int bc = (t & 31) * 4;

    for (int k0 = 0; k0 < K; k0 += 16) {
        int grow = rowBase + ar;
        float4 av;
        if (grow < M) av = *(const float4*)&A[(long)grow * K + k0 + ac];
        else          av = make_float4(0.f, 0.f, 0.f, 0.f);
        *(float4*)&As[ar][ac] = av;
        *(float4*)&Bs[br][bc]     = *(const float4*)&B[(long)(k0 + br) * 128 + bc];
        *(float4*)&Bs[br + 8][bc] = *(const float4*)&B[(long)(k0 + br + 8) * 128 + bc];
        __syncthreads();

#pragma unroll
        for (int k = 0; k < 16; k++) {
            float a[4], b[8];
#pragma unroll
            for (int i = 0; i < 4; i++) a[i] = As[ty * 4 + i][k];
#pragma unroll
            for (int j = 0; j < 8; j++) b[j] = Bs[k][tx * 8 + j];
#pragma unroll
            for (int i = 0; i < 4; i++)
#pragma unroll
                for (int j = 0; j < 8; j++) acc[i][j] = fmaf(a[i], b[j], acc[i][j]);
        }
        __syncthreads();
    }

#pragma unroll
    for (int i = 0; i < 4; i++) {
        int r = rowBase + ty * 4 + i;
        if (r < M) {
            float4 v0 = make_float4(acc[i][0], acc[i][1], acc[i][2], acc[i][3]);
            float4 v1 = make_float4(acc[i][4], acc[i][5], acc[i][6], acc[i][7]);
            *(float4*)&C[(long)r * 128 + tx * 8]     = v0;
            *(float4*)&C[(long)r * 128 + tx * 8 + 4] = v1;
        }
    }
}

// ---------------- layer-1 alpha: warp per node, coalesced float4 loads --------
__global__ void alpha1_kernel(const float* __restrict__ h,
                              const float* __restrict__ a_src,
                              const float* __restrict__ a_dst,
                              float* __restrict__ as_, float* __restrict__ ad_,
                              int n)
{
    int g = blockIdx.x * blockDim.x + threadIdx.x;
    int node = g >> 5, lane = g & 31;
    if (node >= n) return;
    float4 v  = *(const float4*)&h[(long)node * FEAT + lane * 4];
    float4 s4 = *(const float4*)&a_src[lane * 4];   // a_src is [4][32] = 128 floats
    float4 d4 = *(const float4*)&a_dst[lane * 4];
    float ss = v.x * s4.x + v.y * s4.y + v.z * s4.z + v.w * s4.w;
    float sd = v.x * d4.x + v.y * d4.y + v.z * d4.z + v.w * d4.w;
    // segmented reduce over the 8 lanes of each head
#pragma unroll
    for (int o = 4; o >= 1; o >>= 1) {
        ss += __shfl_xor_sync(0xFFFFFFFFu, ss, o);
        sd += __shfl_xor_sync(0xFFFFFFFFu, sd, o);
    }
    if ((lane & 7) == 0) {
        int head = lane >> 3;
        as_[node * HEADS + head] = ss;
        ad_[node * HEADS + head] = sd;
    }
}

// ---------------- layer-2 alpha (warp per node, full reduce) ------------------
__global__ void alpha2_kernel(const float* __restrict__ h,
                              const float* __restrict__ a_src,
                              const float* __restrict__ a_dst,
                              float* __restrict__ as_, float* __restrict__ ad_,
                              int n)
{
    int g = blockIdx.x * blockDim.x + threadIdx.x;
    int node = g >> 5, lane = g & 31;
    if (node >= n) return;
    float4 v  = *(const float4*)&h[(long)node * FEAT + lane * 4];
    float4 s4 = *(const float4*)&a_src[lane * 4];
    float4 d4 = *(const float4*)&a_dst[lane * 4];
    float ss = v.x * s4.x + v.y * s4.y + v.z * s4.z + v.w * s4.w;
    float sd = v.x * d4.x + v.y * d4.y + v.z * d4.z + v.w * d4.w;
#pragma unroll
    for (int o = 16; o > 0; o >>= 1) {
        ss += __shfl_xor_sync(0xFFFFFFFFu, ss, o);
        sd += __shfl_xor_sync(0xFFFFFFFFu, sd, o);
    }
    if (lane == 0) { as_[node] = ss; ad_[node] = sd; }
}

// ---------------- layer-1 FUSED edge pass: w + denom + unnormalized agg -------
// warp per edge; lane -> channels [lane*4, lane*4+4), head = lane>>3
__global__ void edge_fused4_kernel(const int* __restrict__ ei, int E, int Etot,
                                   const float* __restrict__ as_,
                                   const float* __restrict__ ad_,
                                   const float* __restrict__ h,
                                   float* __restrict__ s,
                                   float* __restrict__ out)
{
    int g = blockIdx.x * blockDim.x + threadIdx.x;
    int e = g >> 5, lane = g & 31;
    if (e >= Etot) return;
    int src, dst;
    if (e < E) { src = __ldg(&ei[e]); dst = __ldg(&ei[E + e]); }
    else       { src = dst = e - E; }
    int head = lane >> 3;
    float w = __expf(lrelu(__ldg(&as_[src * HEADS + head]) +
                           __ldg(&ad_[dst * HEADS + head])));
    if ((lane & 7) == 0) red_add_f32(&s[dst * HEADS + head], w);
    float4 v = *(const float4*)&h[(long)src * FEAT + lane * 4];
    red_add_v4(out + (long)dst * FEAT + lane * 4, v.x * w, v.y * w, v.z * w, v.w * w);
}

// ---------------- layer-2 FUSED edge pass (1 head) ----------------------------
__global__ void edge_fused1_kernel(const int* __restrict__ ei, int E, int Etot,
                                   const float* __restrict__ as_,
                                   const float* __restrict__ ad_,
                                   const float* __restrict__ h,
                                   float* __restrict__ s,
                                   float* __restrict__ out)
{
    int g = blockIdx.x * blockDim.x + threadIdx.x;
    int e = g >> 5, lane = g & 31;
    if (e >= Etot) return;
    int src, dst;
    if (e < E) { src = __ldg(&ei[e]); dst = __ldg(&ei[E + e]); }
    else       { src = dst = e - E; }
    float w = __expf(lrelu(__ldg(&as_[src]) + __ldg(&ad_[dst])));
    if (lane == 0) red_add_f32(&s[dst], w);
    float4 v = *(const float4*)&h[(long)src * FEAT + lane * 4];
    red_add_v4(out + (long)dst * FEAT + lane * 4, v.x * w, v.y * w, v.z * w, v.w * w);
}

// ---------------- layer-1 epilogue: normalize + bias + ELU (float4) -----------
__global__ void norm_elu_bias_kernel(float* __restrict__ buf,
                                     const float* __restrict__ s,
                                     const float* __restrict__ b, int n4)
{
    int i = blockIdx.x * blockDim.x + threadIdx.x;   // per float4
    if (i >= n4) return;
    int node = i >> 5, lane4 = i & 31, head = lane4 >> 3;
    float inv = 1.0f / (__ldg(&s[node * HEADS + head]) + 1e-16f);
    float4 v = *(float4*)&buf[i * 4];
    float4 bb = *(const float4*)&b[lane4 * 4];
    v.x = v.x * inv + bb.x;  v.y = v.y * inv + bb.y;
    v.z = v.z * inv + bb.z;  v.w = v.w * inv + bb.w;
    v.x = v.x > 0.f ? v.x : expm1f(v.x);
    v.y = v.y > 0.f ? v.y : expm1f(v.y);
    v.z = v.z > 0.f ? v.z : expm1f(v.z);
    v.w = v.w > 0.f ? v.w : expm1f(v.w);
    *(float4*)&buf[i * 4] = v;
}

// ---------------- layer-2 epilogue: normalize + bias (float4) -----------------
__global__ void norm_bias_kernel(float* __restrict__ buf,
                                 const float* __restrict__ s,
                                 const float* __restrict__ b, int n4)
{
    int i = blockIdx.x * blockDim.x + threadIdx.x;
    if (i >= n4) return;
    int node = i >> 5, lane4 = i & 31;
    float inv = 1.0f / (__ldg(&s[node]) + 1e-16f);
    float4 v = *(float4*)&buf[i * 4];
    float4 bb = *(const float4*)&b[lane4 * 4];
    v.x = v.x * inv + bb.x;  v.y = v.y * inv + bb.y;
    v.z = v.z * inv + bb.z;  v.w = v.w * inv + bb.w;
    *(float4*)&buf[i * 4] = v;
}

// =============================================================================
extern "C" void kernel_launch(void* const* d_in, const int* in_sizes, int n_in,
                              void* d_out, int out_size)
{
    const float* x        = (const float*)d_in[0];
    const int*   ei       = (const int*)  d_in[1];
    const float* W1       = (const float*)d_in[2];
    const float* att_src1 = (const float*)d_in[3];
    const float* att_dst1 = (const float*)d_in[4];
    const float* b1       = (const float*)d_in[5];
    const float* W2       = (const float*)d_in[6];
    const float* att_src2 = (const float*)d_in[7];
    const float* att_dst2 = (const float*)d_in[8];
    const float* b2       = (const float*)d_in[9];
    float* out = (float*)d_out;

    const int N    = in_sizes[0] / IN_DIM;   // 50000
    const int E    = in_sizes[1] / 2;        // 800000
    const int Etot = E + N;                  // 850000

    float *bufA, *bufB, *as_, *ad_, *s_;
    cudaGetSymbolAddress((void**)&bufA, g_bufA);
    cudaGetSymbolAddress((void**)&bufB, g_bufB);
    cudaGetSymbolAddress((void**)&as_,  g_as);
    cudaGetSymbolAddress((void**)&ad_,  g_ad);
    cudaGetSymbolAddress((void**)&s_,   g_s);

    const int edgeBlocks = (int)(((long)Etot * 32 + 255) / 256);

    // ---- Layer 1 ----
    zero_kernel<<<(N * HEADS + 255) / 256, 256>>>(s_, N * HEADS);
    zero_kernel<<<2048, 256>>>(bufB, N * FEAT);

    gemm128_kernel<IN_DIM><<<(N + 63) / 64, 256>>>(x, W1, bufA, N);
    alpha1_kernel<<<(N * 32 + 255) / 256, 256>>>(bufA, att_src1, att_dst1, as_, ad_, N);
    edge_fused4_kernel<<<edgeBlocks, 256>>>(ei, E, Etot, as_, ad_, bufA, s_, bufB);
    norm_elu_bias_kernel<<<(N * 32 + 255) / 256, 256>>>(bufB, s_, b1, N * 32);

    // ---- Layer 2 ----
    zero_kernel<<<(N + 255) / 256, 256>>>(s_, N);
    zero_kernel<<<2048, 256>>>(out, N * FEAT);

    gemm128_kernel<FEAT><<<(N + 63) / 64, 256>>>(bufB, W2, bufA, N);
    alpha2_kernel<<<(N * 32 + 255) / 256, 256>>>(bufA, att_src2, att_dst2, as_, ad_, N);
    edge_fused1_kernel<<<edgeBlocks, 256>>>(ei, E, Etot, as_, ad_, bufA, s_, out);
    norm_bias_kernel<<<(N * 32 + 255) / 256, 256>>>(out, s_, b2, N * 32);
}

// round 5
// speedup vs baseline: 2.3960x; 1.4613x over previous
#include <cuda_runtime.h>
#include <cuda_bf16.h>
#include <math.h>

#define NNODE   50000
#define NEDGE   800000
#define ETOT    (NEDGE + NNODE)
#define IN_DIM  256
#define FEAT    128
#define HEADS   4
#define NHID    32
#define NEG_SLOPE 0.2f
#define NPAD    50176   // NNODE rounded up to multiple of 256

typedef unsigned long long u64;

// ---------------- device scratch (static, no allocation) ----------------
__device__ float g_bufA[NNODE * FEAT];   // h1 then h2
__device__ float g_bufB[NNODE * FEAT];   // elu(h1 agg)
__device__ float g_as[NNODE * HEADS];
__device__ float g_ad[NNODE * HEADS];
__device__ int   g_deg[NPAD];
__device__ int   g_rs[NPAD];             // row starts (exclusive scan of deg)
__device__ int   g_cur[NPAD];            // scatter cursors
__device__ int   g_bsum[256];
__device__ int   g_bsumX[256];
__device__ int   g_ssrc[ETOT];           // src ids sorted by dst

__device__ __forceinline__ float lrelu(float x) { return x > 0.f ? x : NEG_SLOPE * x; }

__device__ __forceinline__ u64 pack2(float lo, float hi) {
    u64 r; asm("mov.b64 %0, {%1, %2};" : "=l"(r) : "f"(lo), "f"(hi)); return r;
}
__device__ __forceinline__ u64 fma2(u64 a, u64 b, u64 c) {
    u64 d; asm("fma.rn.f32x2 %0, %1, %2, %3;" : "=l"(d) : "l"(a), "l"(b), "l"(c)); return d;
}
__device__ __forceinline__ void unpack2(u64 p, float& lo, float& hi) {
    asm("mov.b64 {%0, %1}, %2;" : "=f"(lo), "=f"(hi) : "l"(p));
}

// ---------------- CSR build ----------------
__global__ void zero_int_kernel(int* __restrict__ p, int n) {
    int i = blockIdx.x * blockDim.x + threadIdx.x;
    if (i < n) p[i] = 0;
}

__global__ void hist_kernel(const int* __restrict__ ei, int E, int Etot,
                            int* __restrict__ deg) {
    int e = blockIdx.x * blockDim.x + threadIdx.x;
    if (e >= Etot) return;
    int dst = (e < E) ? __ldg(&ei[E + e]) : (e - E);
    atomicAdd(&deg[dst], 1);
}

// exclusive scan of 256 elements per block; writes block inclusive total to bsum
__global__ void scan_block_kernel(const int* __restrict__ in, int* __restrict__ out,
                                  int* __restrict__ bsum, int n) {
    __shared__ int sh[256];
    int tid = threadIdx.x;
    int i = blockIdx.x * 256 + tid;
    int v = (i < n) ? in[i] : 0;
    sh[tid] = v;
    __syncthreads();
#pragma unroll
    for (int o = 1; o < 256; o <<= 1) {
        int t = (tid >= o) ? sh[tid - o] : 0;
        __syncthreads();
        sh[tid] += t;
        __syncthreads();
    }
    int incl = sh[tid];
    if (i < n) out[i] = incl - v;          // exclusive
    if (bsum && tid == 255) bsum[blockIdx.x] = incl;
}

__global__ void scan_fixup_kernel(int* __restrict__ rs, int* __restrict__ cur,
                                  const int* __restrict__ boff, int n) {
    int i = blockIdx.x * blockDim.x + threadIdx.x;
    if (i >= n) return;
    int v = rs[i] + boff[i >> 8];
    rs[i] = v;
    cur[i] = v;
}

__global__ void scatter_kernel(const int* __restrict__ ei, int E, int Etot,
                               int* __restrict__ cur, int* __restrict__ ssrc) {
    int e = blockIdx.x * blockDim.x + threadIdx.x;
    if (e >= Etot) return;
    int src, dst;
    if (e < E) { src = __ldg(&ei[e]); dst = __ldg(&ei[E + e]); }
    else       { src = dst = e - E; }
    int pos = atomicAdd(&cur[dst], 1);
    ssrc[pos] = src;
}

// ---------------- f32x2 tiled GEMM: C[M,128] = A[M,K] * B[K,128] ----------------
template <int K>
__global__ void __launch_bounds__(256) gemm128_kernel(
    const float* __restrict__ A, const float* __restrict__ B,
    float* __restrict__ C, int M)
{
    __shared__ float As[64][16];
    __shared__ float Bs[16][128];

    const int t  = threadIdx.x;
    const int tx = t & 15;        // 16 col-groups of 8
    const int ty = t >> 4;        // 16 row-groups of 4
    const int rowBase = blockIdx.x * 64;

    u64 acc2[4][4];               // 4 rows x 4 col-pairs (8 cols)
#pragma unroll
    for (int i = 0; i < 4; i++)
#pragma unroll
        for (int j = 0; j < 4; j++) acc2[i][j] = 0ull;

    const int ar = t >> 2;
    const int ac = (t & 3) * 4;
    const int br = t >> 5;
    const int bc = (t & 31) * 4;

    for (int k0 = 0; k0 < K; k0 += 16) {
        int grow = rowBase + ar;
        float4 av;
        if (grow < M) av = *(const float4*)&A[(long)grow * K + k0 + ac];
        else          av = make_float4(0.f, 0.f, 0.f, 0.f);
        *(float4*)&As[ar][ac] = av;
        *(float4*)&Bs[br][bc]     = *(const float4*)&B[(long)(k0 + br) * 128 + bc];
        *(float4*)&Bs[br + 8][bc] = *(const float4*)&B[(long)(k0 + br + 8) * 128 + bc];
        __syncthreads();

#pragma unroll
        for (int k4 = 0; k4 < 4; k4++) {
            float4 a4[4];
#pragma unroll
            for (int i = 0; i < 4; i++)
                a4[i] = *(const float4*)&As[ty * 4 + i][k4 * 4];
#pragma unroll
            for (int kk = 0; kk < 4; kk++) {
                int k = k4 * 4 + kk;
                ulonglong2 bA = *(const ulonglong2*)&Bs[k][tx * 8];
                ulonglong2 bB = *(const ulonglong2*)&Bs[k][tx * 8 + 4];
                u64 bp0 = bA.x, bp1 = bA.y, bp2 = bB.x, bp3 = bB.y;
#pragma unroll
                for (int i = 0; i < 4; i++) {
                    float av_ = (kk == 0) ? a4[i].x : (kk == 1) ? a4[i].y
                              : (kk == 2) ? a4[i].z : a4[i].w;
                    u64 ap = pack2(av_, av_);
                    acc2[i][0] = fma2(ap, bp0, acc2[i][0]);
                    acc2[i][1] = fma2(ap, bp1, acc2[i][1]);
                    acc2[i][2] = fma2(ap, bp2, acc2[i][2]);
                    acc2[i][3] = fma2(ap, bp3, acc2[i][3]);
                }
            }
        }
        __syncthreads();
    }

#pragma unroll
    for (int i = 0; i < 4; i++) {
        int r = rowBase + ty * 4 + i;
        if (r < M) {
            float c[8];
#pragma unroll
            for (int j = 0; j < 4; j++) unpack2(acc2[i][j], c[2 * j], c[2 * j + 1]);
            *(float4*)&C[(long)r * 128 + tx * 8]     = make_float4(c[0], c[1], c[2], c[3]);
            *(float4*)&C[(long)r * 128 + tx * 8 + 4] = make_float4(c[4], c[5], c[6], c[7]);
        }
    }
}

// ---------------- alpha kernels (warp per node) ----------------
__global__ void alpha1_kernel(const float* __restrict__ h,
                              const float* __restrict__ a_src,
                              const float* __restrict__ a_dst,
                              float* __restrict__ as_, float* __restrict__ ad_,
                              int n)
{
    int g = blockIdx.x * blockDim.x + threadIdx.x;
    int node = g >> 5, lane = g & 31;
    if (node >= n) return;
    float4 v  = *(const float4*)&h[(long)node * FEAT + lane * 4];
    float4 s4 = *(const float4*)&a_src[lane * 4];
    float4 d4 = *(const float4*)&a_dst[lane * 4];
    float ss = v.x * s4.x + v.y * s4.y + v.z * s4.z + v.w * s4.w;
    float sd = v.x * d4.x + v.y * d4.y + v.z * d4.z + v.w * d4.w;
#pragma unroll
    for (int o = 4; o >= 1; o >>= 1) {
        ss += __shfl_xor_sync(0xFFFFFFFFu, ss, o);
        sd += __shfl_xor_sync(0xFFFFFFFFu, sd, o);
    }
    if ((lane & 7) == 0) {
        int head = lane >> 3;
        as_[node * HEADS + head] = ss;
        ad_[node * HEADS + head] = sd;
    }
}

__global__ void alpha2_kernel(const float* __restrict__ h,
                              const float* __restrict__ a_src,
                              const float* __restrict__ a_dst,
                              float* __restrict__ as_, float* __restrict__ ad_,
                              int n)
{
    int g = blockIdx.x * blockDim.x + threadIdx.x;
    int node = g >> 5, lane = g & 31;
    if (node >= n) return;
    float4 v  = *(const float4*)&h[(long)node * FEAT + lane * 4];
    float4 s4 = *(const float4*)&a_src[lane * 4];
    float4 d4 = *(const float4*)&a_dst[lane * 4];
    float ss = v.x * s4.x + v.y * s4.y + v.z * s4.z + v.w * s4.w;
    float sd = v.x * d4.x + v.y * d4.y + v.z * d4.z + v.w * d4.w;
#pragma unroll
    for (int o = 16; o > 0; o >>= 1) {
        ss += __shfl_xor_sync(0xFFFFFFFFu, ss, o);
        sd += __shfl_xor_sync(0xFFFFFFFFu, sd, o);
    }
    if (lane == 0) { as_[node] = ss; ad_[node] = sd; }
}

// ---------------- fused gather: softmax-weighted agg + normalize + bias (+ELU) --
// warp per dst node; lane -> channels [lane*4, lane*4+4); H heads
template <int H, int DO_ELU>
__global__ void __launch_bounds__(256) gat_gather_kernel(
    const int* __restrict__ rs, const int* __restrict__ deg,
    const int* __restrict__ ssrc,
    const float* __restrict__ as_, const float* __restrict__ ad_,
    const float* __restrict__ h,  const float* __restrict__ bias,
    float* __restrict__ out, int n)
{
    int g = blockIdx.x * blockDim.x + threadIdx.x;
    int node = g >> 5, lane = g & 31;
    if (node >= n) return;
    const int head = (H == 4) ? (lane >> 3) : 0;

    int start = __ldg(&rs[node]);
    int d     = __ldg(&deg[node]);    // >= 1 (self-loop)
    float adv = __ldg(&ad_[node * H + head]);

    float4 acc = make_float4(0.f, 0.f, 0.f, 0.f);
    float s = 0.f;

    int src = __ldg(&ssrc[start]);
    for (int i = 0; i < d; i++) {
        int nsrc = (i + 1 < d) ? __ldg(&ssrc[start + i + 1]) : 0;
        float w = __expf(lrelu(__ldg(&as_[src * H + head]) + adv));
        s += w;
        float4 v = *(const float4*)&h[(long)src * FEAT + lane * 4];
        acc.x = fmaf(v.x, w, acc.x);
        acc.y = fmaf(v.y, w, acc.y);
        acc.z = fmaf(v.z, w, acc.z);
        acc.w = fmaf(v.w, w, acc.w);
        src = nsrc;
    }

    float inv = 1.0f / (s + 1e-16f);
    float4 b4 = *(const float4*)&bias[lane * 4];
    float4 o;
    o.x = acc.x * inv + b4.x;
    o.y = acc.y * inv + b4.y;
    o.z = acc.z * inv + b4.z;
    o.w = acc.w * inv + b4.w;
    if (DO_ELU) {
        o.x = o.x > 0.f ? o.x : expm1f(o.x);
        o.y = o.y > 0.f ? o.y : expm1f(o.y);
        o.z = o.z > 0.f ? o.z : expm1f(o.z);
        o.w = o.w > 0.f ? o.w : expm1f(o.w);
    }
    *(float4*)&out[(long)node * FEAT + lane * 4] = o;
}

// =============================================================================
extern "C" void kernel_launch(void* const* d_in, const int* in_sizes, int n_in,
                              void* d_out, int out_size)
{
    const float* x        = (const float*)d_in[0];
    const int*   ei       = (const int*)  d_in[1];
    const float* W1       = (const float*)d_in[2];
    const float* att_src1 = (const float*)d_in[3];
    const float* att_dst1 = (const float*)d_in[4];
    const float* b1       = (const float*)d_in[5];
    const float* W2       = (const float*)d_in[6];
    const float* att_src2 = (const float*)d_in[7];
    const float* att_dst2 = (const float*)d_in[8];
    const float* b2       = (const float*)d_in[9];
    float* out = (float*)d_out;

    const int N    = in_sizes[0] / IN_DIM;   // 50000
    const int E    = in_sizes[1] / 2;        // 800000
    const int Etot = E + N;                  // 850000

    float *bufA, *bufB, *as_, *ad_;
    int *deg, *rs, *cur, *bsum, *bsumX, *ssrc;
    cudaGetSymbolAddress((void**)&bufA,  g_bufA);
    cudaGetSymbolAddress((void**)&bufB,  g_bufB);
    cudaGetSymbolAddress((void**)&as_,   g_as);
    cudaGetSymbolAddress((void**)&ad_,   g_ad);
    cudaGetSymbolAddress((void**)&deg,   g_deg);
    cudaGetSymbolAddress((void**)&rs,    g_rs);
    cudaGetSymbolAddress((void**)&cur,   g_cur);
    cudaGetSymbolAddress((void**)&bsum,  g_bsum);
    cudaGetSymbolAddress((void**)&bsumX, g_bsumX);
    cudaGetSymbolAddress((void**)&ssrc,  g_ssrc);

    const int nBlocks256 = (N + 255) / 256;          // 196 for N=50000
    const int eBlocks    = (Etot + 255) / 256;
    const int warpBlocks = (N * 32 + 255) / 256;

    // ---- CSR build (dst-sorted src list) ----
    zero_int_kernel<<<nBlocks256, 256>>>(deg, N);
    hist_kernel<<<eBlocks, 256>>>(ei, E, Etot, deg);
    scan_block_kernel<<<nBlocks256, 256>>>(deg, rs, bsum, N);
    scan_block_kernel<<<1, 256>>>(bsum, bsumX, (int*)nullptr, nBlocks256);
    scan_fixup_kernel<<<nBlocks256, 256>>>(rs, cur, bsumX, N);
    scatter_kernel<<<eBlocks, 256>>>(ei, E, Etot, cur, ssrc);

    // ---- Layer 1 ----
    gemm128_kernel<IN_DIM><<<(N + 63) / 64, 256>>>(x, W1, bufA, N);
    alpha1_kernel<<<warpBlocks, 256>>>(bufA, att_src1, att_dst1, as_, ad_, N);
    gat_gather_kernel<4, 1><<<warpBlocks, 256>>>(rs, deg, ssrc, as_, ad_,
                                                 bufA, b1, bufB, N);

    // ---- Layer 2 ----
    gemm128_kernel<FEAT><<<(N + 63) / 64, 256>>>(bufB, W2, bufA, N);
    alpha2_kernel<<<warpBlocks, 256>>>(bufA, att_src2, att_dst2, as_, ad_, N);
    gat_gather_kernel<1, 0><<<warpBlocks, 256>>>(rs, deg, ssrc, as_, ad_,
                                                 bufA, b2, out, N);
}

// round 6
// speedup vs baseline: 2.6114x; 1.0899x over previous
#include <cuda_runtime.h>
#include <cuda_bf16.h>
#include <math.h>

#define NNODE   50000
#define NEDGE   800000
#define ETOT    (NEDGE + NNODE)
#define IN_DIM  256
#define FEAT    128
#define HEADS   4
#define NHID    32
#define NEG_SLOPE 0.2f
#define NPAD    50176

typedef unsigned long long u64;

// ---------------- device scratch (static, no allocation) ----------------
__device__ float g_bufA[NNODE * FEAT];
__device__ float g_bufB[NNODE * FEAT];
__device__ float g_as[NNODE * HEADS];
__device__ float g_ad[NNODE * HEADS];
__device__ int   g_deg[NPAD];
__device__ int   g_rs[NPAD];
__device__ int   g_cur[NPAD];
__device__ int   g_bsum[256];
__device__ int   g_bsumX[256];
__device__ int   g_ssrc[ETOT];

__device__ __forceinline__ float lrelu(float x) { return x > 0.f ? x : NEG_SLOPE * x; }

__device__ __forceinline__ u64 pack2(float lo, float hi) {
    u64 r; asm("mov.b64 %0, {%1, %2};" : "=l"(r) : "f"(lo), "f"(hi)); return r;
}
__device__ __forceinline__ u64 fma2(u64 a, u64 b, u64 c) {
    u64 d; asm("fma.rn.f32x2 %0, %1, %2, %3;" : "=l"(d) : "l"(a), "l"(b), "l"(c)); return d;
}
__device__ __forceinline__ void unpack2(u64 p, float& lo, float& hi) {
    asm("mov.b64 {%0, %1}, %2;" : "=f"(lo), "=f"(hi) : "l"(p));
}

// ---------------- CSR build ----------------
__global__ void hist_kernel(const int* __restrict__ ei, int E, int Etot,
                            int* __restrict__ deg) {
    int e = blockIdx.x * blockDim.x + threadIdx.x;
    if (e >= Etot) return;
    int dst = (e < E) ? __ldg(&ei[E + e]) : (e - E);
    atomicAdd(&deg[dst], 1);
}

// shfl-based exclusive block scan (256 threads); bsum gets block total
__global__ void scan_block_kernel(const int* __restrict__ in, int* __restrict__ out,
                                  int* __restrict__ bsum, int n) {
    __shared__ int wsum[8];
    int tid = threadIdx.x;
    int lane = tid & 31, w = tid >> 5;
    int i = blockIdx.x * 256 + tid;
    int v = (i < n) ? in[i] : 0;
    int x = v;
#pragma unroll
    for (int o = 1; o < 32; o <<= 1) {
        int t = __shfl_up_sync(0xFFFFFFFFu, x, o);
        if (lane >= o) x += t;
    }
    if (lane == 31) wsum[w] = x;
    __syncthreads();
    if (w == 0) {
        int s = (lane < 8) ? wsum[lane] : 0;
#pragma unroll
        for (int o = 1; o < 8; o <<= 1) {
            int t = __shfl_up_sync(0xFFFFFFFFu, s, o);
            if (lane >= o) s += t;
        }
        if (lane < 8) wsum[lane] = s;
    }
    __syncthreads();
    int woff = (w > 0) ? wsum[w - 1] : 0;
    if (i < n) out[i] = x + woff - v;          // exclusive
    if (bsum && tid == 255) bsum[blockIdx.x] = wsum[7];
}

__global__ void scan_fixup_kernel(int* __restrict__ rs, int* __restrict__ cur,
                                  const int* __restrict__ boff, int n) {
    int i = blockIdx.x * blockDim.x + threadIdx.x;
    if (i >= n) return;
    int v = rs[i] + boff[i >> 8];
    rs[i] = v;
    cur[i] = v;
}

__global__ void scatter_kernel(const int* __restrict__ ei, int E, int Etot,
                               int* __restrict__ cur, int* __restrict__ ssrc) {
    int e = blockIdx.x * blockDim.x + threadIdx.x;
    if (e >= Etot) return;
    int src, dst;
    if (e < E) { src = __ldg(&ei[e]); dst = __ldg(&ei[E + e]); }
    else       { src = dst = e - E; }
    int pos = atomicAdd(&cur[dst], 1);
    ssrc[pos] = src;
}

// ---------------- f32x2 GEMM + fused alpha epilogue ---------------------------
// C[M,128] = A[M,K] * B[K,128]; also as_/ad_ = per-head dots with att vectors.
// H=4: head = tx>>2, reduce over 4 consecutive lanes. H=1: reduce over 16 lanes.
template <int K, int H>
__global__ void __launch_bounds__(256) gemm128_kernel(
    const float* __restrict__ A, const float* __restrict__ B,
    float* __restrict__ C, int M,
    const float* __restrict__ attS, const float* __restrict__ attD,
    float* __restrict__ as_, float* __restrict__ ad_)
{
    __shared__ float As[64][16];
    __shared__ float Bs[16][128];

    const int t  = threadIdx.x;
    const int tx = t & 15;
    const int ty = t >> 4;
    const int rowBase = blockIdx.x * 64;

    u64 acc2[4][4];
#pragma unroll
    for (int i = 0; i < 4; i++)
#pragma unroll
        for (int j = 0; j < 4; j++) acc2[i][j] = 0ull;

    const int ar = t >> 2;
    const int ac = (t & 3) * 4;
    const int br = t >> 5;
    const int bc = (t & 31) * 4;

    for (int k0 = 0; k0 < K; k0 += 16) {
        int grow = rowBase + ar;
        float4 av;
        if (grow < M) av = *(const float4*)&A[(long)grow * K + k0 + ac];
        else          av = make_float4(0.f, 0.f, 0.f, 0.f);
        *(float4*)&As[ar][ac] = av;
        *(float4*)&Bs[br][bc]     = *(const float4*)&B[(long)(k0 + br) * 128 + bc];
        *(float4*)&Bs[br + 8][bc] = *(const float4*)&B[(long)(k0 + br + 8) * 128 + bc];
        __syncthreads();

#pragma unroll
        for (int k4 = 0; k4 < 4; k4++) {
            float4 a4[4];
#pragma unroll
            for (int i = 0; i < 4; i++)
                a4[i] = *(const float4*)&As[ty * 4 + i][k4 * 4];
#pragma unroll
            for (int kk = 0; kk < 4; kk++) {
                int k = k4 * 4 + kk;
                ulonglong2 bA = *(const ulonglong2*)&Bs[k][tx * 8];
                ulonglong2 bB = *(const ulonglong2*)&Bs[k][tx * 8 + 4];
                u64 bp0 = bA.x, bp1 = bA.y, bp2 = bB.x, bp3 = bB.y;
#pragma unroll
                for (int i = 0; i < 4; i++) {
                    float av_ = (kk == 0) ? a4[i].x : (kk == 1) ? a4[i].y
                              : (kk == 2) ? a4[i].z : a4[i].w;
                    u64 ap = pack2(av_, av_);
                    acc2[i][0] = fma2(ap, bp0, acc2[i][0]);
                    acc2[i][1] = fma2(ap, bp1, acc2[i][1]);
                    acc2[i][2] = fma2(ap, bp2, acc2[i][2]);
                    acc2[i][3] = fma2(ap, bp3, acc2[i][3]);
                }
            }
        }
        __syncthreads();
    }

    // att vectors for this thread's 8 channels
    float4 s0 = *(const float4*)&attS[tx * 8];
    float4 s1 = *(const float4*)&attS[tx * 8 + 4];
    float4 d0 = *(const float4*)&attD[tx * 8];
    float4 d1 = *(const float4*)&attD[tx * 8 + 4];

#pragma unroll
    for (int i = 0; i < 4; i++) {
        int r = rowBase + ty * 4 + i;
        float c[8];
#pragma unroll
        for (int j = 0; j < 4; j++) unpack2(acc2[i][j], c[2 * j], c[2 * j + 1]);

        float ss = c[0]*s0.x + c[1]*s0.y + c[2]*s0.z + c[3]*s0.w
                 + c[4]*s1.x + c[5]*s1.y + c[6]*s1.z + c[7]*s1.w;
        float sd = c[0]*d0.x + c[1]*d0.y + c[2]*d0.z + c[3]*d0.w
                 + c[4]*d1.x + c[5]*d1.y + c[6]*d1.z + c[7]*d1.w;
        const int RED = (H == 4) ? 4 : 16;
#pragma unroll
        for (int o = 1; o < RED; o <<= 1) {
            ss += __shfl_xor_sync(0xFFFFFFFFu, ss, o);
            sd += __shfl_xor_sync(0xFFFFFFFFu, sd, o);
        }
        if (r < M) {
            *(float4*)&C[(long)r * 128 + tx * 8]     = make_float4(c[0], c[1], c[2], c[3]);
            *(float4*)&C[(long)r * 128 + tx * 8 + 4] = make_float4(c[4], c[5], c[6], c[7]);
            if ((tx & (RED - 1)) == 0) {
                int head = (H == 4) ? (tx >> 2) : 0;
                as_[r * H + head] = ss;
                ad_[r * H + head] = sd;
            }
        }
    }
}

// ---------------- fused gather: softmax agg + normalize + bias (+ELU) ---------
// warp per dst node; lane -> channels [lane*4, lane*4+4); 4x unrolled edge loop
template <int H, int DO_ELU>
__global__ void __launch_bounds__(256) gat_gather_kernel(
    const int* __restrict__ rs, const int* __restrict__ deg,
    const int* __restrict__ ssrc,
    const float* __restrict__ as_, const float* __restrict__ ad_,
    const float* __restrict__ h,  const float* __restrict__ bias,
    float* __restrict__ out, int n)
{
    int g = blockIdx.x * blockDim.x + threadIdx.x;
    int node = g >> 5, lane = g & 31;
    if (node >= n) return;
    const int head = (H == 4) ? (lane >> 3) : 0;

    int start = __ldg(&rs[node]);
    int d     = __ldg(&deg[node]);
    float adv = __ldg(&ad_[node * H + head]);

    float4 acc = make_float4(0.f, 0.f, 0.f, 0.f);
    float s = 0.f;

    int i = 0;
    for (; i + 4 <= d; i += 4) {
        int i0 = __ldg(&ssrc[start + i]);
        int i1 = __ldg(&ssrc[start + i + 1]);
        int i2 = __ldg(&ssrc[start + i + 2]);
        int i3 = __ldg(&ssrc[start + i + 3]);
        float w0 = __expf(lrelu(__ldg(&as_[i0 * H + head]) + adv));
        float w1 = __expf(lrelu(__ldg(&as_[i1 * H + head]) + adv));
        float w2 = __expf(lrelu(__ldg(&as_[i2 * H + head]) + adv));
        float w3 = __expf(lrelu(__ldg(&as_[i3 * H + head]) + adv));
        float4 v0 = *(const float4*)&h[(long)i0 * FEAT + lane * 4];
        float4 v1 = *(const float4*)&h[(long)i1 * FEAT + lane * 4];
        float4 v2 = *(const float4*)&h[(long)i2 * FEAT + lane * 4];
        float4 v3 = *(const float4*)&h[(long)i3 * FEAT + lane * 4];
        s += (w0 + w1) + (w2 + w3);
        acc.x = fmaf(v0.x, w0, fmaf(v1.x, w1, fmaf(v2.x, w2, fmaf(v3.x, w3, acc.x))));
        acc.y = fmaf(v0.y, w0, fmaf(v1.y, w1, fmaf(v2.y, w2, fmaf(v3.y, w3, acc.y))));
        acc.z = fmaf(v0.z, w0, fmaf(v1.z, w1, fmaf(v2.z, w2, fmaf(v3.z, w3, acc.z))));
        acc.w = fmaf(v0.w, w0, fmaf(v1.w, w1, fmaf(v2.w, w2, fmaf(v3.w, w3, acc.w))));
    }
    for (; i < d; i++) {
        int s0 = __ldg(&ssrc[start + i]);
        float w = __expf(lrelu(__ldg(&as_[s0 * H + head]) + adv));
        float4 v = *(const float4*)&h[(long)s0 * FEAT + lane * 4];
        s += w;
        acc.x = fmaf(v.x, w, acc.x);
        acc.y = fmaf(v.y, w, acc.y);
        acc.z = fmaf(v.z, w, acc.z);
        acc.w = fmaf(v.w, w, acc.w);
    }

    float inv = 1.0f / (s + 1e-16f);
    float4 b4 = *(const float4*)&bias[lane * 4];
    float4 o;
    o.x = acc.x * inv + b4.x;
    o.y = acc.y * inv + b4.y;
    o.z = acc.z * inv + b4.z;
    o.w = acc.w * inv + b4.w;
    if (DO_ELU) {
        o.x = o.x > 0.f ? o.x : expm1f(o.x);
        o.y = o.y > 0.f ? o.y : expm1f(o.y);
        o.z = o.z > 0.f ? o.z : expm1f(o.z);
        o.w = o.w > 0.f ? o.w : expm1f(o.w);
    }
    *(float4*)&out[(long)node * FEAT + lane * 4] = o;
}

// =============================================================================
extern "C" void kernel_launch(void* const* d_in, const int* in_sizes, int n_in,
                              void* d_out, int out_size)
{
    const float* x        = (const float*)d_in[0];
    const int*   ei       = (const int*)  d_in[1];
    const float* W1       = (const float*)d_in[2];
    const float* att_src1 = (const float*)d_in[3];
    const float* att_dst1 = (const float*)d_in[4];
    const float* b1       = (const float*)d_in[5];
    const float* W2       = (const float*)d_in[6];
    const float* att_src2 = (const float*)d_in[7];
    const float* att_dst2 = (const float*)d_in[8];
    const float* b2       = (const float*)d_in[9];
    float* out = (float*)d_out;

    const int N    = in_sizes[0] / IN_DIM;   // 50000
    const int E    = in_sizes[1] / 2;        // 800000
    const int Etot = E + N;                  // 850000

    float *bufA, *bufB, *as_, *ad_;
    int *deg, *rs, *cur, *bsum, *bsumX, *ssrc;
    cudaGetSymbolAddress((void**)&bufA,  g_bufA);
    cudaGetSymbolAddress((void**)&bufB,  g_bufB);
    cudaGetSymbolAddress((void**)&as_,   g_as);
    cudaGetSymbolAddress((void**)&ad_,   g_ad);
    cudaGetSymbolAddress((void**)&deg,   g_deg);
    cudaGetSymbolAddress((void**)&rs,    g_rs);
    cudaGetSymbolAddress((void**)&cur,   g_cur);
    cudaGetSymbolAddress((void**)&bsum,  g_bsum);
    cudaGetSymbolAddress((void**)&bsumX, g_bsumX);
    cudaGetSymbolAddress((void**)&ssrc,  g_ssrc);

    const int nBlocks256 = (N + 255) / 256;
    const int eBlocks    = (Etot + 255) / 256;
    const int warpBlocks = (N * 32 + 255) / 256;

    // ---- CSR build ----
    cudaMemsetAsync(deg, 0, (size_t)N * sizeof(int));
    hist_kernel<<<eBlocks, 256>>>(ei, E, Etot, deg);
    scan_block_kernel<<<nBlocks256, 256>>>(deg, rs, bsum, N);
    scan_block_kernel<<<1, 256>>>(bsum, bsumX, (int*)nullptr, nBlocks256);
    scan_fixup_kernel<<<nBlocks256, 256>>>(rs, cur, bsumX, N);
    scatter_kernel<<<eBlocks, 256>>>(ei, E, Etot, cur, ssrc);

    // ---- Layer 1 ----
    gemm128_kernel<IN_DIM, 4><<<(N + 63) / 64, 256>>>(x, W1, bufA, N,
                                                      att_src1, att_dst1, as_, ad_);
    gat_gather_kernel<4, 1><<<warpBlocks, 256>>>(rs, deg, ssrc, as_, ad_,
                                                 bufA, b1, bufB, N);

    // ---- Layer 2 ----
    gemm128_kernel<FEAT, 1><<<(N + 63) / 64, 256>>>(bufB, W2, bufA, N,
                                                    att_src2, att_dst2, as_, ad_);
    gat_gather_kernel<1, 0><<<warpBlocks, 256>>>(rs, deg, ssrc, as_, ad_,
                                                 bufA, b2, out, N);
}